// round 3
// baseline (speedup 1.0000x reference)
#include <cuda_runtime.h>
#include <math.h>

// Problem constants (fixed by the reference)
#define M_MOL   64
#define N_AT    24
#define P_DESC  276          // 24*23/2
#define T_ROWS  6000
#define NCHUNK  148          // one t-chunk per SM
#define CHUNK   ((T_ROWS + NCHUNK - 1) / NCHUNK)   // 41

#define QCONST  0.22360679774997896f   // sqrt(5)/10
#define CECONST (5.0f / 300.0f)        // 5/(3*sig^2), sig=10

// Scratch (allocation-free rule: __device__ globals)
__device__ float g_xs[M_MOL * P_DESC];
__device__ float g_pG[NCHUNK * M_MOL * P_DESC];   // 10.45 MB partials
__device__ float g_pE[NCHUNK * M_MOL];

// p -> (i, j), lower-triangular pair index (i>j), row-major tril order
__device__ __forceinline__ void pair_ij(int p, int& i, int& j) {
    float f = sqrtf(8.0f * (float)p + 1.0f);
    i = (int)((1.0f + f) * 0.5f);
    while (i * (i - 1) / 2 > p) --i;
    while ((i + 1) * i / 2 <= p) ++i;
    j = p - i * (i - 1) / 2;
}

// ---------------------------------------------------------------------------
// Kernel 1: xs[m, p] = 1 / ||Rs[m,i] - Rs[m,j]||
// ---------------------------------------------------------------------------
__global__ void k_xs(const float* __restrict__ Rs) {
    int m = blockIdx.x;
    int p = threadIdx.x;
    if (p >= P_DESC) return;
    int i, j;
    pair_ij(p, i, j);
    const float* r = Rs + m * N_AT * 3;
    float dx = r[i * 3 + 0] - r[j * 3 + 0];
    float dy = r[i * 3 + 1] - r[j * 3 + 1];
    float dz = r[i * 3 + 2] - r[j * 3 + 2];
    g_xs[m * P_DESC + p] = rsqrtf(dx * dx + dy * dy + dz * dz);
}

// ---------------------------------------------------------------------------
// Kernel 2: main contraction over (m, t, p).
// Grid: NCHUNK blocks (t-chunks) x 512 threads (16 warps).
// Warp w owns molecules m = 4w..4w+3; lane l holds p = 32s + l, s = 0..8.
// All per-m state (q*xs, accumulators) lives in registers; per-t loads are
// coalesced LDG shared across warps via L1. No block sync in the mainloop.
// ---------------------------------------------------------------------------
__global__ __launch_bounds__(512) void k_main(const float* __restrict__ xtr,
                                              const float* __restrict__ jxa) {
    const int c = blockIdx.x;
    const int w = threadIdx.x >> 5;
    const int l = threadIdx.x & 31;
    const int t0 = c * CHUNK;
    const int t1 = min(t0 + CHUNK, T_ROWS);

    bool val[9];
#pragma unroll
    for (int s = 0; s < 9; s++) val[s] = (s * 32 + l) < P_DESC;

    float xq[4][9], acc[4][9], eacc[4];
#pragma unroll
    for (int mm = 0; mm < 4; mm++) {
        const int m = w * 4 + mm;
        eacc[mm] = 0.0f;
#pragma unroll
        for (int s = 0; s < 9; s++) {
            const int p = s * 32 + l;
            xq[mm][s]  = val[s] ? QCONST * g_xs[m * P_DESC + p] : 0.0f;
            acc[mm][s] = 0.0f;
        }
    }

    for (int t = t0; t < t1; t++) {
        float xt[9], jx[9];
        const float* xrow = xtr + (size_t)t * P_DESC;
        const float* jrow = jxa + (size_t)t * P_DESC;
#pragma unroll
        for (int s = 0; s < 9; s++) {
            const int p = s * 32 + l;
            xt[s] = val[s] ? QCONST * __ldg(xrow + p) : 0.0f;
            jx[s] = val[s] ? __ldg(jrow + p) : 0.0f;
        }
#pragma unroll
        for (int mm = 0; mm < 4; mm++) {
            float d2 = 0.0f, dot = 0.0f;
            float df[9];
#pragma unroll
            for (int s = 0; s < 9; s++) {
                df[s] = xq[mm][s] - xt[s];
                d2  = fmaf(df[s], df[s], d2);
                dot = fmaf(df[s], jx[s], dot);
            }
#pragma unroll
            for (int o = 16; o; o >>= 1) {
                d2  += __shfl_xor_sync(0xffffffffu, d2, o);
                dot += __shfl_xor_sync(0xffffffffu, dot, o);
            }
            const float d  = sqrtf(d2);
            const float a  = CECONST * __expf(-d);   // exp_xs
            const float c1 = a * dot;                // F1 weight
            const float c2 = a * (1.0f + d);         // exp1 (F2 weight)
            eacc[mm] = fmaf(c2, dot, eacc[mm]);      // energy term
#pragma unroll
            for (int s = 0; s < 9; s++) {
                acc[mm][s] = fmaf(c1, df[s], acc[mm][s]);
                acc[mm][s] = fmaf(-c2, jx[s], acc[mm][s]);
            }
        }
    }

    // write per-chunk partials
#pragma unroll
    for (int mm = 0; mm < 4; mm++) {
        const int m = w * 4 + mm;
        float* dst = g_pG + ((size_t)c * M_MOL + m) * P_DESC;
#pragma unroll
        for (int s = 0; s < 9; s++) {
            const int p = s * 32 + l;
            if (val[s]) dst[p] = acc[mm][s];
        }
        if (l == 0) g_pE[c * M_MOL + m] = eacc[mm];
    }
}

// ---------------------------------------------------------------------------
// Kernel 3: reduce partials, apply xs^3, scatter to forces, write Es + Fs.
// Output layout: d_out[0:64] = Es, d_out[64 : 64 + 64*24*3] = Fs[m][atom][xyz]
// ---------------------------------------------------------------------------
__global__ void k_fin(const float* __restrict__ Rs, float* __restrict__ out) {
    const int m = blockIdx.x;
    const int tid = threadIdx.x;
    __shared__ float fpair[P_DESC];
    __shared__ float rs[N_AT * 3];

    if (tid < N_AT * 3) rs[tid] = Rs[m * N_AT * 3 + tid];

    if (tid < P_DESC) {
        float g = 0.0f;
        for (int c = 0; c < NCHUNK; c++)
            g += g_pG[((size_t)c * M_MOL + m) * P_DESC + tid];
        const float xs = g_xs[m * P_DESC + tid];
        fpair[tid] = g * xs * xs * xs;   // Fs_x
    }
    if (tid == 0) {
        float e = 0.0f;
        for (int c = 0; c < NCHUNK; c++) e += g_pE[c * M_MOL + m];
        out[m] = e / QCONST;   // * STD(=1) + C(=0)
    }
    __syncthreads();

    if (tid < N_AT * 3) {
        const int b = tid / 3;
        const int k = tid % 3;
        const float rb = rs[b * 3 + k];
        float fb = 0.0f;
        for (int a = 0; a < N_AT; a++) {
            if (a == b) continue;
            const int i = a > b ? a : b;
            const int j = a > b ? b : a;
            const int p = i * (i - 1) / 2 + j;
            fb += (rs[a * 3 + k] - rb) * fpair[p];   // Fs[m,b] = sum_a (R[a]-R[b])*mult
        }
        out[M_MOL + m * N_AT * 3 + tid] = fb;
    }
}

// ---------------------------------------------------------------------------
extern "C" void kernel_launch(void* const* d_in, const int* in_sizes, int n_in,
                              void* d_out, int out_size) {
    const float* Rs  = (const float*)d_in[0];   // [64, 24, 3]
    const float* xtr = (const float*)d_in[1];   // [6000, 276]
    const float* jxa = (const float*)d_in[2];   // [6000, 276]
    float* out = (float*)d_out;                 // [64 + 64*24*3] = 4672 f32

    k_xs<<<M_MOL, 288>>>(Rs);
    k_main<<<NCHUNK, 512>>>(xtr, jxa);
    k_fin<<<M_MOL, 288>>>(Rs, out);
}